// round 1
// baseline (speedup 1.0000x reference)
#include <cuda_runtime.h>

#define BT 640
#define NWARP 20
#define RHO_F 1060.0f
#define CCFL_F 0.9f
#define EPS_AF 1e-6f
#define MAX_CTA 160
#define MAX_T 1056

// Persistent-kernel scratch (no allocations allowed).
__device__ unsigned g_smax_bits[MAX_T];            // per-step global max (float bits, all positive)
__device__ unsigned g_count;                       // grid barrier arrival counter
__device__ float    g_edge[2][MAX_CTA][2][3];      // [buf][cta][left/right edge][A,Q,FQ]

__device__ __forceinline__ unsigned ld_acq_u32(const unsigned* p) {
    unsigned v;
    asm volatile("ld.global.acquire.gpu.u32 %0, [%1];" : "=r"(v) : "l"(p) : "memory");
    return v;
}
__device__ __forceinline__ float ld_acq_f32(const float* p) {
    float v;
    asm volatile("ld.global.acquire.gpu.f32 %0, [%1];" : "=f"(v) : "l"(p) : "memory");
    return v;
}

__global__ void sim_init_kernel() {
    int i = blockIdx.x * blockDim.x + threadIdx.x;
    if (i < MAX_T) g_smax_bits[i] = 0u;
    if (i == 0) g_count = 0u;
}

__global__ void __launch_bounds__(BT, 1) sim_kernel(
    const float* __restrict__ Rs,
    const float* __restrict__ sim_dat,      // (2, M)
    const float* __restrict__ sdc,          // (11, M)
    const float* __restrict__ input_data,   // (T,)
    const int*   __restrict__ strides,      // (3, 2)
    float*       __restrict__ out,          // (T, 3)
    int M, int T)
{
    __shared__ float sA[BT], sQ[BT], sF[BT];
    __shared__ int   wmax[NWARP];
    __shared__ float bc[3];

    const int tid  = threadIdx.x;
    const int cta  = blockIdx.x;
    const int nCTA = gridDim.x;
    const int gi   = cta * BT + tid;
    const bool active = gi < M;
    const int wid  = tid >> 5;

    const int st0 = strides[0], st1 = strides[2], st2 = strides[4];
    const int en0 = strides[1] - 1, en1 = strides[3] - 1, en2 = strides[5] - 1;
    const int mid0 = (strides[0] + strides[1]) >> 1;
    const int mid1 = (strides[2] + strides[3]) >> 1;
    const int mid2 = (strides[4] + strides[5]) >> 1;

    const bool is_start = active && (gi == st0 || gi == st1 || gi == st2);
    const bool is_end   = active && (gi == en0 || gi == en1 || gi == en2);
    const int  midv = (gi == mid0) ? 0 : (gi == mid1) ? 1 : (gi == mid2) ? 2 : -1;

    // Per-point constants + initial state
    float A = 1.0f, Q = 0.0f, invA0 = 1.0f, beta = 1.0f, cc = 1.0f, fqc = 0.0f, Rtot = 1.0f;
    if (active) {
        A = fmaxf(sim_dat[gi], EPS_AF);
        Q = 0.1f * sim_dat[M + gi];
        float A0 = sdc[gi] + 0.5f;
        beta = sdc[M + gi] + 1.0f;
        invA0 = 1.0f / A0;
        cc  = 0.5f * beta / RHO_F;
        fqc = beta * (1.0f / (3.0f * RHO_F)) * invA0;
        if (is_end) {
            float R1 = sdc[7 * M + gi] + 0.5f;
            float R2 = sdc[8 * M + gi] + 0.5f;
            bool m1 = (gi >= strides[2]) && (gi < strides[3]);
            bool m2 = (gi >= strides[4]) && (gi < strides[5]);
            float rsv[4];
#pragma unroll
            for (int j = 0; j < 4; j++) {
                float x = Rs[j];
                rsv[j] = fmaxf(x, 0.0f) + log1pf(expf(-fabsf(x)));   // softplus (jax logaddexp form)
            }
            if (m1)      { R1 *= rsv[0]; R2 *= rsv[1]; }
            else if (m2) { R1 *= rsv[2]; R2 *= rsv[3]; }
            Rtot = R1 + R2;
        }
    }

    // Prologue: evaluate state-0 derived quantities, publish edges + smax[0]
    float sq = 1.0f, FQ = 0.0f, sval = 0.0f;
    if (active) {
        sq = sqrtf(A * invA0);
        float u = Q / A;
        float c = sqrtf(cc * sq);
        sval = fabsf(u) + c;
        FQ = Q * u + fqc * A * sq;
    }
    sA[tid] = A; sQ[tid] = Q; sF[tid] = FQ;
    if (active && tid == 0)      { g_edge[0][cta][0][0] = A; g_edge[0][cta][0][1] = Q; g_edge[0][cta][0][2] = FQ; }
    if (active && tid == BT - 1) { g_edge[0][cta][1][0] = A; g_edge[0][cta][1][1] = Q; g_edge[0][cta][1][2] = FQ; }
    {
        int wv = __reduce_max_sync(0xFFFFFFFFu, __float_as_int(sval));
        if ((tid & 31) == 0) wmax[wid] = wv;
    }
    __syncthreads();
    if (wid == 0) {
        int v = (tid < NWARP) ? wmax[tid] : 0;
        v = __reduce_max_sync(0xFFFFFFFFu, v);
        if (tid == 0) {
            atomicMax((int*)&g_smax_bits[0], v);
            __threadfence();
            atomicAdd(&g_count, 1u);
        }
    }

    for (int t = 0; t < T; ++t) {
        const int buf = t & 1, nbuf = buf ^ 1;

        // ---- grid barrier: wait for smax[t] + step-t edges from all CTAs ----
        if (tid == 0) {
            unsigned target = (unsigned)nCTA * (unsigned)(t + 1);
            while (ld_acq_u32(&g_count) < target) { }
            float smax = __int_as_float((int)ld_acq_u32(&g_smax_bits[t]));
            bc[0] = smax;
            bc[1] = CCFL_F / smax;      // lam = dt/DX = CCFL/smax (DX cancels)
            bc[2] = input_data[t];
        }
        __syncthreads();
        const float smax = bc[0], lam = bc[1], inflow = bc[2];

        // Pre-update pressure (used for mid output + end BC)
        float P = beta * (sq - 1.0f);
        if (midv >= 0) out[t * 3 + midv] = P;

        // Halo reads (step-t state). Cross-CTA edges must bypass stale L1.
        float Al = 0.f, Ql = 0.f, Fl = 0.f, Ar = 0.f, Qr = 0.f, Fr = 0.f;
        if (tid > 0) { Al = sA[tid - 1]; Ql = sQ[tid - 1]; Fl = sF[tid - 1]; }
        else if (cta > 0) {
            Al = ld_acq_f32(&g_edge[buf][cta - 1][1][0]);
            Ql = ld_acq_f32(&g_edge[buf][cta - 1][1][1]);
            Fl = ld_acq_f32(&g_edge[buf][cta - 1][1][2]);
        }
        if (tid < BT - 1) { Ar = sA[tid + 1]; Qr = sQ[tid + 1]; Fr = sF[tid + 1]; }
        else if (cta + 1 < nCTA) {
            Ar = ld_acq_f32(&g_edge[buf][cta + 1][0][0]);
            Qr = ld_acq_f32(&g_edge[buf][cta + 1][0][1]);
            Fr = ld_acq_f32(&g_edge[buf][cta + 1][0][2]);
        }

        // Lax–Friedrichs flux update (interior points only)
        float An = A, Qn = Q;
        if (active && gi > 0 && gi < M - 1) {
            float h = 0.5f * smax;
            float fhA_R = 0.5f * (Q + Qr) - h * (Ar - A);
            float fhA_L = 0.5f * (Ql + Q) - h * (A - Al);
            float fhQ_R = 0.5f * (FQ + Fr) - h * (Qr - Q);
            float fhQ_L = 0.5f * (Fl + FQ) - h * (Q - Ql);
            An = A - lam * (fhA_R - fhA_L);
            Qn = Q - lam * (fhQ_R - fhQ_L);
        }
        if (is_start) Qn = inflow;
        if (is_end)   Qn = P / Rtot;
        An = fmaxf(An, EPS_AF);

        // New-state derived quantities (feeds smax[t+1], next-step fluxes, next P)
        A = An; Q = Qn;
        float snew = 0.0f;
        if (active) {
            sq = sqrtf(A * invA0);
            float u = Q / A;
            float c = sqrtf(cc * sq);
            snew = fabsf(u) + c;
            FQ = Q * u + fqc * A * sq;
        }

        // Publish edges for next step (double-buffered; race-free via barrier spacing)
        if (active && tid == 0)      { g_edge[nbuf][cta][0][0] = A; g_edge[nbuf][cta][0][1] = Q; g_edge[nbuf][cta][0][2] = FQ; }
        if (active && tid == BT - 1) { g_edge[nbuf][cta][1][0] = A; g_edge[nbuf][cta][1][1] = Q; g_edge[nbuf][cta][1][2] = FQ; }

        int wv = __reduce_max_sync(0xFFFFFFFFu, __float_as_int(snew));
        if ((tid & 31) == 0) wmax[wid] = wv;
        __syncthreads();                         // old smem reads done; wmax ready
        sA[tid] = A; sQ[tid] = Q; sF[tid] = FQ;  // publish new state to smem (next iter reads after its barrier)
        if (wid == 0) {
            int v = (tid < NWARP) ? wmax[tid] : 0;
            v = __reduce_max_sync(0xFFFFFFFFu, v);
            if (tid == 0) {
                atomicMax((int*)&g_smax_bits[t + 1], v);
                __threadfence();                 // release: covers edge STGs (ordered via bar.sync) + smax
                atomicAdd(&g_count, 1u);
            }
        }
    }
}

extern "C" void kernel_launch(void* const* d_in, const int* in_sizes, int n_in,
                              void* d_out, int out_size) {
    const float* Rs         = (const float*)d_in[0];
    const float* sim_dat    = (const float*)d_in[1];
    const float* sdc        = (const float*)d_in[2];
    const float* input_data = (const float*)d_in[3];
    const int*   strides    = (const int*)d_in[4];

    int M = in_sizes[1] / 2;     // sim_dat is (2, M)
    int T = in_sizes[3];         // input_data length

    int nCTA = (M + BT - 1) / BT;   // 141 for M=90000 — <= 148 SMs, all co-resident

    sim_init_kernel<<<(MAX_T + 255) / 256, 256>>>();
    sim_kernel<<<nCTA, BT>>>(Rs, sim_dat, sdc, input_data, strides, (float*)d_out, M, T);
}